// round 6
// baseline (speedup 1.0000x reference)
#include <cuda_runtime.h>
#include <cuda_bf16.h>
#include <cuda_fp16.h>
#include <cstdint>

// ============================================================================
// Problem constants
// ============================================================================
#define NROWS 16384
#define DDIM  128
#define TILE  128
#define NJOBS 16384              // 128 row-blocks x 128 col-tiles

static __device__ __nv_bfloat16 g_Abf[NROWS * DDIM];  // normalized * C_EXP
static __device__ __nv_bfloat16 g_Pbf[NROWS * DDIM];  // normalized
static __device__ float g_partS[NROWS];   // per-row expsum (atomic-accumulated)
static __device__ float g_diagv[NROWS];   // scaled diag: C_EXP * dot
static __device__ float g_acc;

#define C_EXP   20.609929155556620f   // log2(e) / 0.07 (folded into A)
#define LN2     0.69314718055994531f  // diag: dot/T = (C_EXP*dot) * ln2

// SMEM: 3 rotating 128x128 bf16 slabs (272B padded rows). Slab @0 holds the
// A tile at segment start, then rejoins the B rotation (frags are in regs).
#define ROWB   272
#define SLAB   34816
#define SMEM_TOTAL (3 * 34816)

// ============================================================================
// PTX helpers (sm_80+ portable; ptxas target is plain sm_100 -> no tcgen05)
// ============================================================================
__device__ __forceinline__ uint32_t smem_to_u32(const void* p) {
    uint32_t a;
    asm("{ .reg .u64 t; cvta.to.shared.u64 t, %1; cvt.u32.u64 %0, t; }" : "=r"(a) : "l"(p));
    return a;
}
__device__ __forceinline__ float ex2f_fast(float x) {
    float y; asm("ex2.approx.ftz.f32 %0, %1;" : "=f"(y) : "f"(x)); return y;
}
// pack two f32 -> f16x2, ex2 both halves, accumulate
__device__ __forceinline__ uint32_t cvt_f16x2(float a, float b) {
    uint32_t r; asm("cvt.rn.f16x2.f32 %0, %1, %2;" : "=r"(r) : "f"(a), "f"(b)); return r;
}
__device__ __forceinline__ uint32_t ex2_f16x2(uint32_t x) {
    uint32_t y; asm("ex2.approx.f16x2 %0, %1;" : "=r"(y) : "r"(x)); return y;
}
__device__ __forceinline__ uint32_t hadd2(uint32_t a, uint32_t b) {
    uint32_t r; asm("add.f16x2 %0, %1, %2;" : "=r"(r) : "r"(a), "r"(b)); return r;
}
__device__ __forceinline__ float h2sum(uint32_t h) {
    __half2 v = *reinterpret_cast<__half2*>(&h);
    float2 f = __half22float2(v);
    return f.x + f.y;
}

#define LDSM_X4(r0, r1, r2, r3, addr) \
    asm volatile("ldmatrix.sync.aligned.m8n8.x4.shared.b16 {%0,%1,%2,%3}, [%4];" \
        : "=r"(r0), "=r"(r1), "=r"(r2), "=r"(r3) : "r"(addr))

#define MMA_BF16(d, a, b0, b1) \
    asm volatile("mma.sync.aligned.m16n8k16.row.col.f32.bf16.bf16.f32 " \
        "{%0,%1,%2,%3},{%4,%5,%6,%7},{%8,%9},{%0,%1,%2,%3};" \
        : "+f"((d)[0]), "+f"((d)[1]), "+f"((d)[2]), "+f"((d)[3]) \
        : "r"((a)[0]), "r"((a)[1]), "r"((a)[2]), "r"((a)[3]), "r"(b0), "r"(b1))

#define CP_ASYNC16(saddr, gptr) \
    asm volatile("cp.async.cg.shared.global [%0], [%1], 16;" :: "r"(saddr), "l"(gptr))
#define CP_COMMIT() asm volatile("cp.async.commit_group;")
#define CP_WAIT1()  asm volatile("cp.async.wait_group 1;")
#define CP_WAIT2()  asm volatile("cp.async.wait_group 2;")

// ============================================================================
// Kernel 1: normalize rows (fp32) -> bf16 (A scaled by C_EXP); zero partS+acc
// ============================================================================
__global__ void __launch_bounds__(256) normalize_kernel(const float* __restrict__ A,
                                                        const float* __restrict__ P) {
    int gid = blockIdx.x * blockDim.x + threadIdx.x;
    if (gid == 0) g_acc = 0.0f;
    if (gid < NROWS) g_partS[gid] = 0.0f;
    int warp = gid >> 5;
    int lane = threadIdx.x & 31;
    if (warp >= 2 * NROWS) return;
    const float* src;
    __nv_bfloat16* dst;
    float extra;
    if (warp < NROWS) {
        src = A + (size_t)warp * DDIM; dst = g_Abf + (size_t)warp * DDIM; extra = C_EXP;
    } else {
        int r = warp - NROWS;
        src = P + (size_t)r * DDIM; dst = g_Pbf + (size_t)r * DDIM; extra = 1.0f;
    }
    float4 v = reinterpret_cast<const float4*>(src)[lane];
    float ss = v.x * v.x + v.y * v.y + v.z * v.z + v.w * v.w;
    #pragma unroll
    for (int o = 16; o > 0; o >>= 1) ss += __shfl_xor_sync(0xFFFFFFFFu, ss, o);
    float s = extra / fmaxf(sqrtf(ss), 1e-12f);
    __nv_bfloat162 h0 = __floats2bfloat162_rn(v.x * s, v.y * s);
    __nv_bfloat162 h1 = __floats2bfloat162_rn(v.z * s, v.w * s);
    reinterpret_cast<__nv_bfloat162*>(dst)[lane * 2 + 0] = h0;
    reinterpret_cast<__nv_bfloat162*>(dst)[lane * 2 + 1] = h1;
}

// ============================================================================
// cp.async loader: 128x128 bf16 tile (row-major) -> padded SMEM (272B rows)
// ============================================================================
__device__ __forceinline__ void cp_tile(uint32_t sbase, const __nv_bfloat16* gsrc, int tid) {
    const char* g = reinterpret_cast<const char*>(gsrc);
    #pragma unroll
    for (int i = 0; i < 8; i++) {
        int idx = tid + i * 256;          // 2048 chunks of 16B
        int row = idx >> 4;
        int c   = idx & 15;
        uint32_t s = sbase + row * ROWB + c * 16;
        CP_ASYNC16(s, g + idx * 16);
    }
}

// ============================================================================
// Kernel 2: persistent balanced fused GEMM + exp rowsum + diag.
// acc = C_EXP * dot directly (A pre-scaled) -> exp2 arg with no FMUL.
// Fast epilogue: f16x2 pack + ex2.f16x2 + hadd2; half2 partials per row,
// flushed to f32 per tile. Diag tile takes a separate f32 epilogue.
// ============================================================================
__global__ void __launch_bounds__(256, 2) infonce_main_kernel() {
    extern __shared__ char smem[];
    uint32_t sb = smem_to_u32(smem);
    int tid = threadIdx.x;
    int lane = tid & 31;
    int w = tid >> 5;
    int wr = w >> 1;            // row-group 0..3 (32 rows)
    int wc = w & 1;             // col-group 0..1 (64 cols)

    int G = gridDim.x;
    int j0 = (int)(((long long)blockIdx.x * NJOBS) / G);
    int j1 = (int)(((long long)(blockIdx.x + 1) * NJOBS) / G);

    int g = lane >> 2;
    int tig = lane & 3;
    uint32_t b_lane_off = (uint32_t)(((lane & 7) + ((lane >> 4) << 3)) * ROWB
                                     + ((lane >> 3) & 1) * 16)
                          + (uint32_t)(wc * 64) * ROWB;
    const uint32_t bufoff[3] = {SLAB, 2 * SLAB, 0};

    int j = j0;
    while (j < j1) {
        int rb = j >> 7;
        int c0 = j & 127;
        int cend = min(j1 - (rb << 7), 128);
        int nt = cend - c0;

        __syncthreads();   // previous segment's smem is free

        cp_tile(sb + 0, g_Abf + (size_t)rb * TILE * DDIM, tid);
        CP_COMMIT();
        cp_tile(sb + bufoff[0], g_Pbf + (size_t)c0 * TILE * DDIM, tid);
        CP_COMMIT();
        if (nt > 1)
            cp_tile(sb + bufoff[1], g_Pbf + (size_t)(c0 + 1) * TILE * DDIM, tid);
        CP_COMMIT();
        CP_WAIT2();
        __syncthreads();

        uint32_t afrag[8][2][4];
        #pragma unroll
        for (int f = 0; f < 2; f++) {
            uint32_t a_addr = sb + (wr * 32 + f * 16 + (lane & 15)) * ROWB + (lane >> 4) * 16;
            #pragma unroll
            for (int k = 0; k < 8; k++)
                LDSM_X4(afrag[k][f][0], afrag[k][f][1], afrag[k][f][2], afrag[k][f][3],
                        a_addr + k * 32);
        }

        float S[4] = {0.f, 0.f, 0.f, 0.f};
        float d[4] = {0.f, 0.f, 0.f, 0.f};
        int curbuf = 0, nxtbuf = 2;

        for (int t = 0; t < nt; t++) {
            CP_WAIT1();
            __syncthreads();
            if (t + 2 < nt)
                cp_tile(sb + bufoff[nxtbuf], g_Pbf + (size_t)(c0 + t + 2) * TILE * DDIM, tid);
            CP_COMMIT();

            uint32_t bbase = sb + bufoff[curbuf] + b_lane_off;

            if (c0 + t != rb) {
                // ---- fast path: no diag ----
                uint32_t hS0 = 0u, hS1 = 0u, hS2 = 0u, hS3 = 0u;  // half2 partials
                #pragma unroll
                for (int c = 0; c < 4; c++) {
                    float acc[2][2][4];
                    #pragma unroll
                    for (int f = 0; f < 2; f++)
                        #pragma unroll
                        for (int nb = 0; nb < 2; nb++)
                            #pragma unroll
                            for (int q = 0; q < 4; q++) acc[f][nb][q] = 0.0f;

                    uint32_t bchunk = bbase + (uint32_t)(c * 16) * ROWB;
                    #pragma unroll
                    for (int k = 0; k < 8; k++) {
                        uint32_t b0, b1, b2, b3;
                        LDSM_X4(b0, b1, b2, b3, bchunk + k * 32);
                        MMA_BF16(acc[0][0], afrag[k][0], b0, b1);
                        MMA_BF16(acc[0][1], afrag[k][0], b2, b3);
                        MMA_BF16(acc[1][0], afrag[k][1], b0, b1);
                        MMA_BF16(acc[1][1], afrag[k][1], b2, b3);
                    }
                    #pragma unroll
                    for (int f = 0; f < 2; f++)
                        #pragma unroll
                        for (int nb = 0; nb < 2; nb++) {
                            uint32_t e0 = ex2_f16x2(cvt_f16x2(acc[f][nb][0], acc[f][nb][1]));
                            uint32_t e1 = ex2_f16x2(cvt_f16x2(acc[f][nb][2], acc[f][nb][3]));
                            if (f == 0) { hS0 = hadd2(hS0, e0); hS1 = hadd2(hS1, e1); }
                            else        { hS2 = hadd2(hS2, e0); hS3 = hadd2(hS3, e1); }
                        }
                }
                S[0] += h2sum(hS0); S[1] += h2sum(hS1);
                S[2] += h2sum(hS2); S[3] += h2sum(hS3);
            } else {
                // ---- diag tile: f32 epilogue with capture ----
                #pragma unroll
                for (int c = 0; c < 4; c++) {
                    float acc[2][2][4];
                    #pragma unroll
                    for (int f = 0; f < 2; f++)
                        #pragma unroll
                        for (int nb = 0; nb < 2; nb++)
                            #pragma unroll
                            for (int q = 0; q < 4; q++) acc[f][nb][q] = 0.0f;

                    uint32_t bchunk = bbase + (uint32_t)(c * 16) * ROWB;
                    #pragma unroll
                    for (int k = 0; k < 8; k++) {
                        uint32_t b0, b1, b2, b3;
                        LDSM_X4(b0, b1, b2, b3, bchunk + k * 32);
                        MMA_BF16(acc[0][0], afrag[k][0], b0, b1);
                        MMA_BF16(acc[0][1], afrag[k][0], b2, b3);
                        MMA_BF16(acc[1][0], afrag[k][1], b0, b1);
                        MMA_BF16(acc[1][1], afrag[k][1], b2, b3);
                    }
                    #pragma unroll
                    for (int f = 0; f < 2; f++)
                        #pragma unroll
                        for (int nb = 0; nb < 2; nb++)
                            #pragma unroll
                            for (int q = 0; q < 4; q++) {
                                float v = acc[f][nb][q];
                                int hi = q >> 1;
                                S[f * 2 + hi] += ex2f_fast(v);
                                int col_local = wc * 64 + c * 16 + nb * 8 + tig * 2 + (q & 1);
                                int row_local = wr * 32 + f * 16 + hi * 8 + g;
                                if (col_local == row_local) d[f * 2 + hi] = v;
                            }
                }
            }
            if (++curbuf == 3) curbuf = 0;
            if (++nxtbuf == 3) nxtbuf = 0;
        }

        // flush: reduce across the 4 threads sharing each row, then atomics
        #pragma unroll
        for (int i = 0; i < 4; i++) {
            S[i] += __shfl_xor_sync(0xFFFFFFFFu, S[i], 1);
            S[i] += __shfl_xor_sync(0xFFFFFFFFu, S[i], 2);
            d[i] += __shfl_xor_sync(0xFFFFFFFFu, d[i], 1);
            d[i] += __shfl_xor_sync(0xFFFFFFFFu, d[i], 2);
        }
        if (tig == 0) {
            int seg_has_diag = (rb >= c0) && (rb < cend);
            int wrote_diag = seg_has_diag && ((wr >> 1) == wc);
            #pragma unroll
            for (int i = 0; i < 4; i++) {
                int row_local = wr * 32 + (i >> 1) * 16 + (i & 1) * 8 + g;
                int row = rb * TILE + row_local;
                atomicAdd(&g_partS[row], S[i]);
                if (wrote_diag) g_diagv[row] = d[i];
            }
        }
        j += nt;
    }
}

// ============================================================================
// Kernel 3: per-row loss + global reduction  (diag is C_EXP*dot -> *ln2 = dot/T)
// ============================================================================
__global__ void __launch_bounds__(256) rowsum_kernel() {
    int row = blockIdx.x * 256 + threadIdx.x;
    float v = logf(g_partS[row]) - g_diagv[row] * LN2;
    #pragma unroll
    for (int o = 16; o > 0; o >>= 1) v += __shfl_xor_sync(0xFFFFFFFFu, v, o);
    __shared__ float red[8];
    int lane = threadIdx.x & 31, wid = threadIdx.x >> 5;
    if (lane == 0) red[wid] = v;
    __syncthreads();
    if (wid == 0) {
        float s = (lane < 8) ? red[lane] : 0.0f;
        #pragma unroll
        for (int o = 4; o > 0; o >>= 1) s += __shfl_xor_sync(0xFFFFFFFFu, s, o);
        if (lane == 0) atomicAdd(&g_acc, s);
    }
}

// ============================================================================
// Kernel 4: finalize
// ============================================================================
__global__ void finalize_kernel(float* out) {
    out[0] = g_acc * (1.0f / (float)NROWS);
}

// ============================================================================
// Launch
// ============================================================================
extern "C" void kernel_launch(void* const* d_in, const int* in_sizes, int n_in,
                              void* d_out, int out_size) {
    const float* A = (const float*)d_in[0];
    const float* P = (const float*)d_in[1];
    int nsm = 148;
    cudaDeviceGetAttribute(&nsm, cudaDevAttrMultiProcessorCount, 0);
    cudaFuncSetAttribute(infonce_main_kernel,
                         cudaFuncAttributeMaxDynamicSharedMemorySize, SMEM_TOTAL);
    normalize_kernel<<<(2 * NROWS) / 8, 256>>>(A, P);
    infonce_main_kernel<<<2 * nsm, 256, SMEM_TOTAL>>>();
    rowsum_kernel<<<NROWS / 256, 256>>>();
    finalize_kernel<<<1, 1>>>((float*)d_out);
}